// round 7
// baseline (speedup 1.0000x reference)
#include <cuda_runtime.h>
#include <cuda_bf16.h>
#include <math_constants.h>

// Problem constants
#define BATCH 128
#define CIN   256
#define CHID  1024
#define HW    17
#define NPIX  289                 // 17*17
#define MDIM  36992               // 128*289
#define KDIM  2304                // 256*9
#define NDIM  1024
#define NTILES 8                  // 1024/128
#define KBLOCKS 144               // 2304/16

// Scratch (device globals — allocation-free rule)
__device__ __align__(16) float g_xt[BATCH * NPIX * CIN];      // [b, p, c]
__device__ __align__(16) float g_wt[KDIM * NDIM];             // [k, n], k = seg*256 + c
__device__ float g_spart[NTILES * MDIM];                      // [ntile, m]

// ---------------------------------------------------------------------------
// Kernel 1: x [B, C, H, W] -> xt [B, H*W, C]  (32x32 smem tile transpose)
// ---------------------------------------------------------------------------
__global__ void transpose_x_kernel(const float* __restrict__ x) {
    __shared__ float tile[32][33];
    int b = blockIdx.z;
    int cbase = blockIdx.x * 32;      // 8 blocks cover 256
    int pbase = blockIdx.y * 32;      // 10 blocks cover 289
    int tx = threadIdx.x, ty = threadIdx.y;   // (32, 8)
    const float* xb = x + (size_t)b * CIN * NPIX;
#pragma unroll
    for (int r = 0; r < 4; r++) {
        int c = cbase + ty + r * 8;
        int p = pbase + tx;
        tile[ty + r * 8][tx] = (p < NPIX) ? xb[c * NPIX + p] : 0.f;
    }
    __syncthreads();
    float* xtb = g_xt + (size_t)b * NPIX * CIN;
#pragma unroll
    for (int r = 0; r < 4; r++) {
        int p = pbase + ty + r * 8;
        int c = cbase + tx;
        if (p < NPIX) xtb[p * CIN + c] = tile[tx][ty + r * 8];
    }
}

// ---------------------------------------------------------------------------
// Kernel 2: w_rnn [n, c, dy, dx] -> wt [k, n], k = (dy*3+dx)*256 + c
// ---------------------------------------------------------------------------
__global__ void transpose_w_kernel(const float* __restrict__ w) {
    int gid = blockIdx.x * 256 + threadIdx.x;
    if (gid >= KDIM * NDIM) return;
    int n = gid & 1023;
    int k = gid >> 10;
    int seg = k >> 8;        // dy*3+dx
    int c   = k & 255;
    g_wt[k * NDIM + n] = w[n * KDIM + c * 9 + seg];
}

// ---------------------------------------------------------------------------
// Packed f32x2 helpers (Blackwell FFMA2 — PTX-only path)
// ---------------------------------------------------------------------------
__device__ __forceinline__ void fma2(unsigned long long& d,
                                     unsigned long long a,
                                     unsigned long long b) {
    asm("fma.rn.f32x2 %0, %1, %2, %0;" : "+l"(d) : "l"(a), "l"(b));
}
__device__ __forceinline__ unsigned long long pack2(float lo, float hi) {
    unsigned long long r;
    asm("mov.b64 %0, {%1, %2};" : "=l"(r) : "f"(lo), "f"(hi));
    return r;
}
__device__ __forceinline__ unsigned long long dup2(float f) {
    unsigned long long r;
    asm("mov.b64 %0, {%1, %1};" : "=l"(r) : "f"(f));
    return r;
}

// ---------------------------------------------------------------------------
// Kernel 3: implicit-GEMM conv + fused (bias, tanh, relu, w_out-dot) epilogue
//   C[m, n] = sum_k A[m,k] * B[k,n];  A = im2col(xt), B = wt
//   s_part[nt, m] = sum over 128 local n of w_out[n]*relu(tanh(C + b_rnn[n]))
// grid (NTILES=8, 289), block 256
// ---------------------------------------------------------------------------
__global__ __launch_bounds__(256, 2)
void gemm_kernel(const float* __restrict__ b_rnn, const float* __restrict__ w_out) {
    __shared__ float As[2][16][132];
    __shared__ float Bs[2][16][132];
    __shared__ float red[16][129];

    int tx = threadIdx.x;
    int nt = blockIdx.x;
    int mt = blockIdx.y;
    int m0 = mt * 128;
    int n0 = nt * 128;

    // --- A-load mapping: per thread 2 float4 along k (lw), rows lr, lr+64
    int lw = tx & 3;          // which float4 of the 16-wide k block
    int lr = tx >> 2;         // 0..63
    int rb[2], ryy[2], rxx[2];
#pragma unroll
    for (int e = 0; e < 2; e++) {
        int m = m0 + lr + e * 64;
        int bb = m / NPIX;
        int p  = m - bb * NPIX;
        int y  = p / HW;
        rb[e] = bb; ryy[e] = y; rxx[e] = p - y * HW;
    }

    // --- B-load mapping
    int bw = tx & 31;         // float4 along n
    int bk = tx >> 5;         // 0..7; rows bk, bk+8

    // --- compute fragment mapping
    int tm = tx >> 4;         // 0..15 -> rows tm*8..tm*8+7
    int tn = tx & 15;         // 0..15 -> cols tn*8..tn*8+7

    unsigned long long acc[4][8];
#pragma unroll
    for (int q = 0; q < 4; q++)
#pragma unroll
        for (int j = 0; j < 8; j++) acc[q][j] = 0ull;

    float4 areg[2], breg[2];

    auto loadAB = [&](int kb) {
        int k0  = kb * 16;
        int seg = k0 >> 8;
        int c0  = (k0 & 255) + lw * 4;
        int dy  = seg / 3 - 1;
        int dx  = seg - (seg / 3) * 3 - 1;
#pragma unroll
        for (int e = 0; e < 2; e++) {
            int yy = ryy[e] + dy;
            int xx = rxx[e] + dx;
            if ((unsigned)yy < (unsigned)HW && (unsigned)xx < (unsigned)HW) {
                areg[e] = *(const float4*)&g_xt[(((size_t)rb[e] * HW + yy) * HW + xx) * CIN + c0];
            } else {
                areg[e] = make_float4(0.f, 0.f, 0.f, 0.f);
            }
        }
#pragma unroll
        for (int e = 0; e < 2; e++) {
            int k = k0 + bk + e * 8;
            breg[e] = *(const float4*)&g_wt[(size_t)k * NDIM + n0 + bw * 4];
        }
    };

    auto storeAB = [&](int s) {
#pragma unroll
        for (int e = 0; e < 2; e++) {
            int mloc = lr + e * 64;
            As[s][lw * 4 + 0][mloc] = areg[e].x;
            As[s][lw * 4 + 1][mloc] = areg[e].y;
            As[s][lw * 4 + 2][mloc] = areg[e].z;
            As[s][lw * 4 + 3][mloc] = areg[e].w;
            *(float4*)&Bs[s][bk + e * 8][bw * 4] = breg[e];
        }
    };

    // prologue
    loadAB(0);
    storeAB(0);
    __syncthreads();

    for (int kb = 0; kb < KBLOCKS; kb++) {
        int cur = kb & 1;
        bool more = (kb + 1) < KBLOCKS;
        if (more) loadAB(kb + 1);

#pragma unroll
        for (int kk = 0; kk < 16; kk++) {
            float4 a0 = *(const float4*)&As[cur][kk][tm * 8];
            float4 a1 = *(const float4*)&As[cur][kk][tm * 8 + 4];
            float4 b0 = *(const float4*)&Bs[cur][kk][tn * 8];
            float4 b1 = *(const float4*)&Bs[cur][kk][tn * 8 + 4];
            unsigned long long pa[4];
            pa[0] = pack2(a0.x, a0.y);
            pa[1] = pack2(a0.z, a0.w);
            pa[2] = pack2(a1.x, a1.y);
            pa[3] = pack2(a1.z, a1.w);
            unsigned long long pb[8];
            pb[0] = dup2(b0.x); pb[1] = dup2(b0.y);
            pb[2] = dup2(b0.z); pb[3] = dup2(b0.w);
            pb[4] = dup2(b1.x); pb[5] = dup2(b1.y);
            pb[6] = dup2(b1.z); pb[7] = dup2(b1.w);
#pragma unroll
            for (int q = 0; q < 4; q++)
#pragma unroll
                for (int j = 0; j < 8; j++) fma2(acc[q][j], pa[q], pb[j]);
        }

        if (more) storeAB((kb + 1) & 1);
        __syncthreads();
    }

    // Epilogue: bias + tanh + relu + w_out dot over this thread's 8 n-cols.
    // b_rnn/w_out loaded HERE (not before the mainloop) to keep 16 registers
    // out of the hot loop's live set (launch_bounds caps us at 128 regs).
    float brf[8], wof[8];
#pragma unroll
    for (int j = 0; j < 8; j++) {
        brf[j] = b_rnn[n0 + tn * 8 + j];
        wof[j] = w_out[n0 + tn * 8 + j];
    }

#pragma unroll
    for (int i = 0; i < 8; i++) {
        int q = i >> 1, h = i & 1;
        float sum = 0.f;
#pragma unroll
        for (int j = 0; j < 8; j++) {
            unsigned long long u = acc[q][j];
            float v = __uint_as_float(h ? (unsigned)(u >> 32) : (unsigned)u);
            v += brf[j];
            v = tanhf(v);
            v = v > 0.f ? v : 0.f;
            sum = fmaf(wof[j], v, sum);
        }
        red[tn][tm * 8 + i] = sum;
    }
    __syncthreads();

    if (tx < 128) {
        float tot = 0.f;
#pragma unroll
        for (int t = 0; t < 16; t++) tot += red[t][tx];
        g_spart[nt * MDIM + m0 + tx] = tot;
    }
}

// ---------------------------------------------------------------------------
// Kernel 4: finalize — sum partials + b_out, sigmoid -> score; argmax -> pos
// grid 128, block 512
// pos written as FLOAT VALUES (0..16 exactly representable) — harness output
// buffer is the __output__ dtype (float32); reference int32 pos cast to float
// compares exactly.
// ---------------------------------------------------------------------------
__global__ void finalize_kernel(const float* __restrict__ b_out, float* __restrict__ out) {
    __shared__ float sv[512];
    __shared__ int   si[512];
    int b = blockIdx.x;
    int tid = threadIdx.x;

    float s = -CUDART_INF_F;
    if (tid < NPIX) {
        float acc = b_out[0];
#pragma unroll
        for (int t = 0; t < NTILES; t++) acc += g_spart[t * MDIM + b * NPIX + tid];
        s = acc;
        out[b * NPIX + tid] = 1.f / (1.f + expf(-acc));   // sigmoid score
    }
    sv[tid] = s;
    si[tid] = tid;
    __syncthreads();
    for (int off = 256; off > 0; off >>= 1) {
        if (tid < off) {
            float v2 = sv[tid + off]; int i2 = si[tid + off];
            if (v2 > sv[tid] || (v2 == sv[tid] && i2 < si[tid])) {
                sv[tid] = v2; si[tid] = i2;
            }
        }
        __syncthreads();
    }
    if (tid == 0) {
        int idx = si[0];
        out[MDIM + b * 2 + 0] = (float)(idx / HW);   // y
        out[MDIM + b * 2 + 1] = (float)(idx % HW);   // x
    }
}

// ---------------------------------------------------------------------------
extern "C" void kernel_launch(void* const* d_in, const int* in_sizes, int n_in,
                              void* d_out, int out_size) {
    const float* x     = (const float*)d_in[0];
    const float* w_rnn = (const float*)d_in[1];
    const float* b_rnn = (const float*)d_in[2];
    const float* w_out = (const float*)d_in[3];
    const float* b_out = (const float*)d_in[4];
    float* out = (float*)d_out;

    transpose_x_kernel<<<dim3(8, 10, 128), dim3(32, 8)>>>(x);
    transpose_w_kernel<<<(KDIM * NDIM + 255) / 256, 256>>>(w_rnn);
    gemm_kernel<<<dim3(NTILES, MDIM / 128), 256>>>(b_rnn, w_out);
    finalize_kernel<<<BATCH, 512>>>(b_out, out);
}

// round 9
// speedup vs baseline: 1.8477x; 1.8477x over previous
#include <cuda_runtime.h>
#include <cuda_bf16.h>
#include <math_constants.h>
#include <cstdint>

// ---------------------------------------------------------------------------
// Problem constants
// ---------------------------------------------------------------------------
#define BATCH 128
#define CIN   256
#define HW    17
#define NPIX  289                 // 17*17
#define MDIM  36992               // 128*289 = 289 * 128 exactly
#define KDIM  2304                // 256*9
#define NDIM  1024

// GEMM tiling
#define BM    128
#define BN    128
#define BK    32                  // k per stage (two k16 halves)
#define ITERS (KDIM / BK)         // 72
#define MTILES (MDIM / BM)        // 289 (exact)
#define NTILES (NDIM / BN)        // 8

// SMEM stage layout: rows padded to 80B (5 x 16B units; 5 coprime 8 ->
// conflict-free ldmatrix). Ah, Al, Bh, Bl each 128 rows x 80B = 10240B.
#define ROWB   80
#define MATB   10240
#define STAGEB (4 * MATB)         // 40960
#define SMEM_HDR 1024
#define SMEM_TOT (SMEM_HDR + 2 * STAGEB)   // 82944

// ---------------------------------------------------------------------------
// Scratch (device globals — allocation-free rule)
// ---------------------------------------------------------------------------
__device__ __align__(16) __nv_bfloat16 g_xh[(size_t)BATCH * NPIX * CIN];
__device__ __align__(16) __nv_bfloat16 g_xl[(size_t)BATCH * NPIX * CIN];
__device__ __align__(16) __nv_bfloat16 g_wh[(size_t)NDIM * KDIM];   // [n][k]
__device__ __align__(16) __nv_bfloat16 g_wl[(size_t)NDIM * KDIM];
__device__ float g_spart[NTILES * MDIM];

// ---------------------------------------------------------------------------
// PTX helpers (baseline ISA only — no sm_103a-variant instructions)
// ---------------------------------------------------------------------------
__device__ __forceinline__ uint32_t smem_u32_of(const void* p) {
    uint32_t a;
    asm("{ .reg .u64 t; cvta.to.shared.u64 t, %1; cvt.u32.u64 %0, t; }"
        : "=r"(a) : "l"(p));
    return a;
}
__device__ __forceinline__ void cp16(uint32_t dst, const void* src, uint32_t sz) {
    asm volatile("cp.async.cg.shared.global [%0], [%1], 16, %2;"
                 :: "r"(dst), "l"(src), "r"(sz) : "memory");
}
__device__ __forceinline__ void cp_commit() {
    asm volatile("cp.async.commit_group;" ::: "memory");
}
__device__ __forceinline__ void cp_wait1() {
    asm volatile("cp.async.wait_group 1;" ::: "memory");
}
__device__ __forceinline__ void cp_wait0() {
    asm volatile("cp.async.wait_group 0;" ::: "memory");
}
__device__ __forceinline__ void ldm_x4(uint32_t* r, uint32_t addr) {
    asm volatile("ldmatrix.sync.aligned.m8n8.x4.shared.b16 {%0,%1,%2,%3}, [%4];"
                 : "=r"(r[0]), "=r"(r[1]), "=r"(r[2]), "=r"(r[3]) : "r"(addr));
}
__device__ __forceinline__ void mma16816(float* d, const uint32_t* a,
                                         const uint32_t* b) {
    asm volatile(
        "mma.sync.aligned.m16n8k16.row.col.f32.bf16.bf16.f32 "
        "{%0,%1,%2,%3}, {%4,%5,%6,%7}, {%8,%9}, {%0,%1,%2,%3};"
        : "+f"(d[0]), "+f"(d[1]), "+f"(d[2]), "+f"(d[3])
        : "r"(a[0]), "r"(a[1]), "r"(a[2]), "r"(a[3]), "r"(b[0]), "r"(b[1]));
}

// ---------------------------------------------------------------------------
// Kernel 1: x NCHW -> [b, p, c] split into bf16 hi/lo
// ---------------------------------------------------------------------------
__global__ void transpose_x_split(const float* __restrict__ x) {
    __shared__ float tile[32][33];
    int b = blockIdx.z;
    int cb = blockIdx.x * 32;       // 8 blocks cover 256
    int pb = blockIdx.y * 32;       // 10 blocks cover 289
    int tx = threadIdx.x, ty = threadIdx.y;   // (32, 8)
    const float* xb = x + (size_t)b * CIN * NPIX;
#pragma unroll
    for (int r = 0; r < 4; r++) {
        int c = cb + ty + r * 8;
        int p = pb + tx;
        tile[ty + r * 8][tx] = (p < NPIX) ? xb[c * NPIX + p] : 0.f;
    }
    __syncthreads();
    size_t ob = (size_t)b * NPIX * CIN;
#pragma unroll
    for (int r = 0; r < 4; r++) {
        int p = pb + ty + r * 8;
        int c = cb + tx;
        if (p < NPIX) {
            float v = tile[tx][ty + r * 8];
            __nv_bfloat16 h = __float2bfloat16(v);
            g_xh[ob + (size_t)p * CIN + c] = h;
            g_xl[ob + (size_t)p * CIN + c] =
                __float2bfloat16(v - __bfloat162float(h));
        }
    }
}

// ---------------------------------------------------------------------------
// Kernel 2: w_rnn [n, c, 3, 3] -> [n][k], k = seg*256 + c, bf16 hi/lo
// ---------------------------------------------------------------------------
__global__ void w_split_kernel(const float* __restrict__ w) {
    int gid = blockIdx.x * 256 + threadIdx.x;
    if (gid >= NDIM * KDIM) return;
    int k = gid % KDIM;
    int n = gid / KDIM;
    int seg = k >> 8;
    int c   = k & 255;
    float v = w[(size_t)n * KDIM + c * 9 + seg];
    __nv_bfloat16 h = __float2bfloat16(v);
    g_wh[gid] = h;
    g_wl[gid] = __float2bfloat16(v - __bfloat162float(h));
}

// ---------------------------------------------------------------------------
// Kernel 3: mma.sync bf16-split implicit-GEMM conv + fused epilogue
// grid (8, 289), block 256 (8 warps: 4 m-warps x 2 n-warps)
// ---------------------------------------------------------------------------
__global__ __launch_bounds__(256, 1)
void gemm_mma_kernel(const float* __restrict__ b_rnn, const float* __restrict__ w_out) {
    extern __shared__ char smem[];
    uint32_t su = smem_u32_of(smem);
    uint32_t st_base = su + SMEM_HDR;

    int tid = threadIdx.x;
    int wid = tid >> 5, lane = tid & 31;
    int wm = wid & 3;        // m-warp: rows wm*32..+31
    int wn = wid >> 2;       // n-warp: cols wn*64..+63
    int g  = lane >> 2;      // group row 0..7
    int tg = lane & 3;       // thread-in-group (k/n pair index)
    int nt = blockIdx.x, mt = blockIdx.y;
    int n0 = nt * BN;

    // ---- per-thread load coordinates ----
    int arow[2], acb[2], abb[2], ayy[2], axx[2];
#pragma unroll
    for (int i = 0; i < 2; i++) {
        int id = i * 256 + tid;         // 0..511
        arow[i] = id >> 2;              // 0..127
        acb[i]  = id & 3;               // 16B chunk within 64B row
        int m = mt * BM + arow[i];
        abb[i] = m / NPIX;
        int p = m - abb[i] * NPIX;
        ayy[i] = p / HW;
        axx[i] = p - ayy[i] * HW;
    }
    int brow[2], bcb[2];
#pragma unroll
    for (int i = 0; i < 2; i++) {
        int id = i * 256 + tid;
        brow[i] = id >> 2;
        bcb[i]  = id & 3;
    }

    auto loadStage = [&](int it, int s) {
        uint32_t sb = st_base + s * STAGEB;
        int k0  = it * BK;
        int seg = k0 >> 8;
        int c0  = k0 & 255;
        int dy  = seg / 3 - 1;
        int dx  = seg - (seg / 3) * 3 - 1;
#pragma unroll
        for (int i = 0; i < 2; i++) {
            int yy = ayy[i] + dy, xx = axx[i] + dx;
            bool v = ((unsigned)yy < (unsigned)HW) && ((unsigned)xx < (unsigned)HW);
            size_t goff = ((size_t)abb[i] * NPIX + yy * HW + xx) * CIN + c0 + acb[i] * 8;
            uint32_t dst = sb + arow[i] * ROWB + acb[i] * 16;
            uint32_t sz = v ? 16u : 0u;
            cp16(dst,        v ? (const void*)(g_xh + goff) : (const void*)g_xh, sz);
            cp16(dst + MATB, v ? (const void*)(g_xl + goff) : (const void*)g_xl, sz);
        }
#pragma unroll
        for (int i = 0; i < 2; i++) {
            size_t goff = (size_t)(n0 + brow[i]) * KDIM + k0 + bcb[i] * 8;
            uint32_t dst = sb + 2 * MATB + brow[i] * ROWB + bcb[i] * 16;
            cp16(dst,        g_wh + goff, 16);
            cp16(dst + MATB, g_wl + goff, 16);
        }
    };

    float acc[2][8][4];
#pragma unroll
    for (int tm = 0; tm < 2; tm++)
#pragma unroll
        for (int tn = 0; tn < 8; tn++)
#pragma unroll
            for (int c = 0; c < 4; c++) acc[tm][tn][c] = 0.f;

    auto computeStage = [&](int s) {
        uint32_t sb = st_base + s * STAGEB;
#pragma unroll
        for (int kk = 0; kk < 2; kk++) {
            uint32_t aH[2][4], aL[2][4], bH[8][2], bL[8][2];
            // A fragments: 16x16 tiles, canonical x4 address pattern
#pragma unroll
            for (int tm = 0; tm < 2; tm++) {
                int row = wm * 32 + tm * 16 + (lane & 15);
                int cbl = kk * 2 + (lane >> 4);
                uint32_t ad = sb + row * ROWB + cbl * 16;
                ldm_x4(aH[tm], ad);
                ldm_x4(aL[tm], ad + MATB);
            }
            // B fragments: two adjacent 8-wide n-tiles per x4
#pragma unroll
            for (int tp = 0; tp < 4; tp++) {
                int row = wn * 64 + tp * 16 + ((lane >> 3) & 1) * 8 + (lane & 7);
                int cbl = kk * 2 + (lane >> 4);
                uint32_t bd = sb + 2 * MATB + row * ROWB + cbl * 16;
                uint32_t r[4];
                ldm_x4(r, bd);
                bH[2 * tp][0] = r[0]; bH[2 * tp][1] = r[2];
                bH[2 * tp + 1][0] = r[1]; bH[2 * tp + 1][1] = r[3];
                ldm_x4(r, bd + MATB);
                bL[2 * tp][0] = r[0]; bL[2 * tp][1] = r[2];
                bL[2 * tp + 1][0] = r[1]; bL[2 * tp + 1][1] = r[3];
            }
#pragma unroll
            for (int tm = 0; tm < 2; tm++)
#pragma unroll
                for (int tn = 0; tn < 8; tn++) {
                    mma16816(acc[tm][tn], aH[tm], bH[tn]);   // hi*hi
                    mma16816(acc[tm][tn], aH[tm], bL[tn]);   // hi*lo
                    mma16816(acc[tm][tn], aL[tm], bH[tn]);   // lo*hi
                }
        }
    };

    // ---- pipeline: double-buffered cp.async ----
    loadStage(0, 0);
    cp_commit();
    for (int it = 0; it < ITERS; it++) {
        int cur = it & 1;
        if (it + 1 < ITERS) {
            loadStage(it + 1, cur ^ 1);
            cp_commit();
            cp_wait1();
        } else {
            cp_wait0();
        }
        __syncthreads();
        computeStage(cur);
        __syncthreads();
    }

    // ---- epilogue: bias + tanh + relu + w_out dot ----
    float* sbias = (float*)smem;                    // [0, 512)
    float* swout = (float*)(smem + 512);            // [512, 1024)
    float* red   = (float*)(smem + SMEM_HDR);       // 2 x 128 floats (stage0)
    if (tid < BN) {
        sbias[tid] = b_rnn[n0 + tid];
        swout[tid] = w_out[n0 + tid];
    }
    __syncthreads();

#pragma unroll
    for (int tm = 0; tm < 2; tm++) {
        float sumA = 0.f, sumB = 0.f;   // rows g and g+8 of this 16-row tile
#pragma unroll
        for (int tn = 0; tn < 8; tn++) {
            int col = wn * 64 + tn * 8 + tg * 2;
#pragma unroll
            for (int h = 0; h < 2; h++) {
                float bi = sbias[col + h];
                float wo = swout[col + h];
                float vA = tanhf(acc[tm][tn][h] + bi);
                vA = fmaxf(vA, 0.f);
                sumA = fmaf(wo, vA, sumA);
                float vB = tanhf(acc[tm][tn][2 + h] + bi);
                vB = fmaxf(vB, 0.f);
                sumB = fmaf(wo, vB, sumB);
            }
        }
        // reduce across the 4 threads of the k-group (tg = lane&3)
#pragma unroll
        for (int off = 1; off < 4; off <<= 1) {
            sumA += __shfl_xor_sync(0xffffffffu, sumA, off);
            sumB += __shfl_xor_sync(0xffffffffu, sumB, off);
        }
        if (tg == 0) {
            int rowA = wm * 32 + tm * 16 + g;
            red[wn * 128 + rowA]     = sumA;
            red[wn * 128 + rowA + 8] = sumB;
        }
    }
    __syncthreads();

    if (tid < BM) {
        float tot = red[tid] + red[128 + tid];
        g_spart[nt * MDIM + mt * BM + tid] = tot;
    }
}

// ---------------------------------------------------------------------------
// Kernel 4: finalize — sum 8 partials + b_out, sigmoid -> score; argmax -> pos
// pos written as float values (0..16 exactly representable in fp32)
// ---------------------------------------------------------------------------
__global__ void finalize_kernel(const float* __restrict__ b_out, float* __restrict__ out) {
    __shared__ float sv[512];
    __shared__ int   si[512];
    int b = blockIdx.x;
    int tid = threadIdx.x;

    float s = -CUDART_INF_F;
    if (tid < NPIX) {
        float acc = b_out[0];
#pragma unroll
        for (int t = 0; t < NTILES; t++) acc += g_spart[t * MDIM + b * NPIX + tid];
        s = acc;
        out[b * NPIX + tid] = 1.f / (1.f + expf(-acc));   // sigmoid score
    }
    sv[tid] = s;
    si[tid] = tid;
    __syncthreads();
    for (int off = 256; off > 0; off >>= 1) {
        if (tid < off) {
            float v2 = sv[tid + off]; int i2 = si[tid + off];
            if (v2 > sv[tid] || (v2 == sv[tid] && i2 < si[tid])) {
                sv[tid] = v2; si[tid] = i2;
            }
        }
        __syncthreads();
    }
    if (tid == 0) {
        int idx = si[0];
        out[MDIM + b * 2 + 0] = (float)(idx / HW);   // y
        out[MDIM + b * 2 + 1] = (float)(idx % HW);   // x
    }
}

// ---------------------------------------------------------------------------
extern "C" void kernel_launch(void* const* d_in, const int* in_sizes, int n_in,
                              void* d_out, int out_size) {
    const float* x     = (const float*)d_in[0];
    const float* w_rnn = (const float*)d_in[1];
    const float* b_rnn = (const float*)d_in[2];
    const float* w_out = (const float*)d_in[3];
    const float* b_out = (const float*)d_in[4];
    float* out = (float*)d_out;

    cudaFuncSetAttribute(gemm_mma_kernel,
                         cudaFuncAttributeMaxDynamicSharedMemorySize, SMEM_TOT);

    transpose_x_split<<<dim3(8, 10, 128), dim3(32, 8)>>>(x);
    w_split_kernel<<<(NDIM * KDIM + 255) / 256, 256>>>(w_rnn);
    gemm_mma_kernel<<<dim3(NTILES, MTILES), 256, SMEM_TOT>>>(b_rnn, w_out);
    finalize_kernel<<<BATCH, 512>>>(b_out, out);
}

// round 16
// speedup vs baseline: 2.1236x; 1.1493x over previous
#include <cuda_runtime.h>
#include <cuda_bf16.h>
#include <math_constants.h>
#include <cstdint>

// ---------------------------------------------------------------------------
// Problem constants
// ---------------------------------------------------------------------------
#define BATCH 128
#define CIN   256
#define HW    17
#define NPIX  289                 // 17*17
#define MDIM  36992               // 128*289 = 289 * 128 exactly
#define KDIM  2304                // 256*9
#define NDIM  1024

// GEMM tiling
#define BM    128
#define BN    128
#define BK    64                  // k per stage (four k16 sub-steps); 64 | 256
#define ITERS (KDIM / BK)         // 36
#define MTILES (MDIM / BM)        // 289 (exact)
#define NTILES (NDIM / BN)        // 8
#define NSTAGE 3

// SMEM stage layout: rows padded to 144B (9 x 16B units; 9 coprime 8 ->
// conflict-free ldmatrix; bank shift 36 mod 32 = 4 per row -> distinct banks).
// Ah, Al, Bh, Bl each 128 rows x 144B = 18432B.
#define ROWB   144
#define MATB   18432
#define STAGEB (4 * MATB)         // 73728
#define SMEM_HDR 1024
#define SMEM_TOT (SMEM_HDR + NSTAGE * STAGEB)   // 222208

// ---------------------------------------------------------------------------
// Scratch (device globals — allocation-free rule)
// ---------------------------------------------------------------------------
__device__ __align__(16) __nv_bfloat16 g_xh[(size_t)BATCH * NPIX * CIN];
__device__ __align__(16) __nv_bfloat16 g_xl[(size_t)BATCH * NPIX * CIN];
__device__ __align__(16) __nv_bfloat16 g_wh[(size_t)NDIM * KDIM];   // [n][k]
__device__ __align__(16) __nv_bfloat16 g_wl[(size_t)NDIM * KDIM];
__device__ float g_spart[NTILES * MDIM];

// ---------------------------------------------------------------------------
// PTX helpers (baseline ISA only — compute_103-safe, no sm_103a variants)
// ---------------------------------------------------------------------------
__device__ __forceinline__ uint32_t smem_u32_of(const void* p) {
    uint32_t a;
    asm("{ .reg .u64 t; cvta.to.shared.u64 t, %1; cvt.u32.u64 %0, t; }"
        : "=r"(a) : "l"(p));
    return a;
}
__device__ __forceinline__ void cp16(uint32_t dst, const void* src, uint32_t sz) {
    asm volatile("cp.async.cg.shared.global [%0], [%1], 16, %2;"
                 :: "r"(dst), "l"(src), "r"(sz) : "memory");
}
__device__ __forceinline__ void cp_commit() {
    asm volatile("cp.async.commit_group;" ::: "memory");
}
__device__ __forceinline__ void cp_wait1() {
    asm volatile("cp.async.wait_group 1;" ::: "memory");
}
__device__ __forceinline__ void cp_wait0() {
    asm volatile("cp.async.wait_group 0;" ::: "memory");
}
__device__ __forceinline__ void ldm_x4(uint32_t* r, uint32_t addr) {
    asm volatile("ldmatrix.sync.aligned.m8n8.x4.shared.b16 {%0,%1,%2,%3}, [%4];"
                 : "=r"(r[0]), "=r"(r[1]), "=r"(r[2]), "=r"(r[3]) : "r"(addr));
}
__device__ __forceinline__ void mma16816(float* d, const uint32_t* a,
                                         const uint32_t* b) {
    asm volatile(
        "mma.sync.aligned.m16n8k16.row.col.f32.bf16.bf16.f32 "
        "{%0,%1,%2,%3}, {%4,%5,%6,%7}, {%8,%9}, {%0,%1,%2,%3};"
        : "+f"(d[0]), "+f"(d[1]), "+f"(d[2]), "+f"(d[3])
        : "r"(a[0]), "r"(a[1]), "r"(a[2]), "r"(a[3]), "r"(b[0]), "r"(b[1]));
}

// ---------------------------------------------------------------------------
// Kernel 1: x NCHW -> [b, p, c] split into bf16 hi/lo
// ---------------------------------------------------------------------------
__global__ void transpose_x_split(const float* __restrict__ x) {
    __shared__ float tile[32][33];
    int b = blockIdx.z;
    int cb = blockIdx.x * 32;
    int pb = blockIdx.y * 32;
    int tx = threadIdx.x, ty = threadIdx.y;   // (32, 8)
    const float* xb = x + (size_t)b * CIN * NPIX;
#pragma unroll
    for (int r = 0; r < 4; r++) {
        int c = cb + ty + r * 8;
        int p = pb + tx;
        tile[ty + r * 8][tx] = (p < NPIX) ? xb[c * NPIX + p] : 0.f;
    }
    __syncthreads();
    size_t ob = (size_t)b * NPIX * CIN;
#pragma unroll
    for (int r = 0; r < 4; r++) {
        int p = pb + ty + r * 8;
        int c = cb + tx;
        if (p < NPIX) {
            float v = tile[tx][ty + r * 8];
            __nv_bfloat16 h = __float2bfloat16(v);
            g_xh[ob + (size_t)p * CIN + c] = h;
            g_xl[ob + (size_t)p * CIN + c] =
                __float2bfloat16(v - __bfloat162float(h));
        }
    }
}

// ---------------------------------------------------------------------------
// Kernel 2: w_rnn [n, c, 3, 3] -> [n][k], k = seg*256 + c, bf16 hi/lo
// ---------------------------------------------------------------------------
__global__ void w_split_kernel(const float* __restrict__ w) {
    int gid = blockIdx.x * 256 + threadIdx.x;
    if (gid >= NDIM * KDIM) return;
    int k = gid % KDIM;
    int n = gid / KDIM;
    int seg = k >> 8;
    int c   = k & 255;
    float v = w[(size_t)n * KDIM + c * 9 + seg];
    __nv_bfloat16 h = __float2bfloat16(v);
    g_wh[gid] = h;
    g_wl[gid] = __float2bfloat16(v - __bfloat162float(h));
}

// ---------------------------------------------------------------------------
// Kernel 3: mma.sync bf16-split implicit-GEMM conv + fused epilogue
// grid (8, 289), block 256 (8 warps: 4 m-warps x 2 n-warps)
// 3-stage cp.async pipeline, one __syncthreads per k-iteration.
// ---------------------------------------------------------------------------
__global__ __launch_bounds__(256, 1)
void gemm_mma_kernel(const float* __restrict__ b_rnn, const float* __restrict__ w_out) {
    extern __shared__ char smem[];
    uint32_t su = smem_u32_of(smem);
    uint32_t st_base = su + SMEM_HDR;

    int tid = threadIdx.x;
    int wid = tid >> 5, lane = tid & 31;
    int wm = wid & 3;        // m-warp: rows wm*32..+31
    int wn = wid >> 2;       // n-warp: cols wn*64..+63
    int g  = lane >> 2;      // group row 0..7
    int tg = lane & 3;       // thread-in-group
    int nt = blockIdx.x, mt = blockIdx.y;
    int n0 = nt * BN;

    // ---- per-thread load coordinates: 4 slots of (row, chunk) over 128x8 ----
    int arow[4], ach[4], abb[4], ayy[4], axx[4];
#pragma unroll
    for (int i = 0; i < 4; i++) {
        int slot = i * 256 + tid;       // 0..1023
        arow[i] = slot >> 3;            // 0..127
        ach[i]  = slot & 7;             // 16B chunk within 128B row
        int m = mt * BM + arow[i];
        abb[i] = m / NPIX;
        int p = m - abb[i] * NPIX;
        ayy[i] = p / HW;
        axx[i] = p - ayy[i] * HW;
    }

    auto loadStage = [&](int it, int s) {
        uint32_t sb = st_base + s * STAGEB;
        int k0  = it * BK;
        int seg = k0 >> 8;              // BK=64 divides 256 -> single seg
        int c0  = k0 & 255;
        int dy  = seg / 3 - 1;
        int dx  = seg - (seg / 3) * 3 - 1;
#pragma unroll
        for (int i = 0; i < 4; i++) {
            int row = arow[i], ch = ach[i];
            uint32_t dst = sb + row * ROWB + ch * 16;
            // A (with im2col halo)
            int yy = ayy[i] + dy, xx = axx[i] + dx;
            bool v = ((unsigned)yy < (unsigned)HW) && ((unsigned)xx < (unsigned)HW);
            size_t goff = ((size_t)abb[i] * NPIX + yy * HW + xx) * CIN + c0 + ch * 8;
            uint32_t sz = v ? 16u : 0u;
            cp16(dst,        v ? (const void*)(g_xh + goff) : (const void*)g_xh, sz);
            cp16(dst + MATB, v ? (const void*)(g_xl + goff) : (const void*)g_xl, sz);
            // B
            size_t boff = (size_t)(n0 + row) * KDIM + k0 + ch * 8;
            cp16(dst + 2 * MATB, g_wh + boff, 16);
            cp16(dst + 3 * MATB, g_wl + boff, 16);
        }
    };

    float acc[2][8][4];
#pragma unroll
    for (int tm = 0; tm < 2; tm++)
#pragma unroll
        for (int tn = 0; tn < 8; tn++)
#pragma unroll
            for (int c = 0; c < 4; c++) acc[tm][tn][c] = 0.f;

    auto computeStage = [&](int s) {
        uint32_t sb = st_base + s * STAGEB;
#pragma unroll
        for (int kk = 0; kk < 4; kk++) {
            uint32_t aH[2][4], aL[2][4], bH[8][2], bL[8][2];
#pragma unroll
            for (int tm = 0; tm < 2; tm++) {
                int row = wm * 32 + tm * 16 + (lane & 15);
                int cbl = kk * 2 + (lane >> 4);
                uint32_t ad = sb + row * ROWB + cbl * 16;
                ldm_x4(aH[tm], ad);
                ldm_x4(aL[tm], ad + MATB);
            }
#pragma unroll
            for (int tp = 0; tp < 4; tp++) {
                int row = wn * 64 + tp * 16 + ((lane >> 3) & 1) * 8 + (lane & 7);
                int cbl = kk * 2 + (lane >> 4);
                uint32_t bd = sb + 2 * MATB + row * ROWB + cbl * 16;
                uint32_t r[4];
                ldm_x4(r, bd);
                bH[2 * tp][0] = r[0]; bH[2 * tp][1] = r[2];
                bH[2 * tp + 1][0] = r[1]; bH[2 * tp + 1][1] = r[3];
                ldm_x4(r, bd + MATB);
                bL[2 * tp][0] = r[0]; bL[2 * tp][1] = r[2];
                bL[2 * tp + 1][0] = r[1]; bL[2 * tp + 1][1] = r[3];
            }
#pragma unroll
            for (int tm = 0; tm < 2; tm++)
#pragma unroll
                for (int tn = 0; tn < 8; tn++) {
                    mma16816(acc[tm][tn], aH[tm], bH[tn]);   // hi*hi
                    mma16816(acc[tm][tn], aH[tm], bL[tn]);   // hi*lo
                    mma16816(acc[tm][tn], aL[tm], bH[tn]);   // lo*hi
                }
        }
    };

    // ---- pipeline: 3-stage, one barrier per iteration ----
    loadStage(0, 0);
    cp_commit();
    loadStage(1, 1);
    cp_commit();

    for (int it = 0; it < ITERS; it++) {
        cp_wait1();                 // stage `it` complete (<=1 group pending)
        __syncthreads();            // data visible; slot (it+2)%3 free
        if (it + 2 < ITERS) loadStage(it + 2, (it + 2) % NSTAGE);
        cp_commit();                // keep group counting uniform
        computeStage(it % NSTAGE);
    }
    cp_wait0();
    __syncthreads();

    // ---- epilogue: bias + tanh + relu + w_out dot ----
    float* sbias = (float*)smem;                    // [0, 512)
    float* swout = (float*)(smem + 512);            // [512, 1024)
    float* red   = (float*)(smem + SMEM_HDR);       // 2 x 128 floats
    if (tid < BN) {
        sbias[tid] = b_rnn[n0 + tid];
        swout[tid] = w_out[n0 + tid];
    }
    __syncthreads();

#pragma unroll
    for (int tm = 0; tm < 2; tm++) {
        float sumA = 0.f, sumB = 0.f;   // rows g and g+8 of this 16-row tile
#pragma unroll
        for (int tn = 0; tn < 8; tn++) {
            int col = wn * 64 + tn * 8 + tg * 2;
#pragma unroll
            for (int h = 0; h < 2; h++) {
                float bi = sbias[col + h];
                float wo = swout[col + h];
                float vA = tanhf(acc[tm][tn][h] + bi);
                vA = fmaxf(vA, 0.f);
                sumA = fmaf(wo, vA, sumA);
                float vB = tanhf(acc[tm][tn][2 + h] + bi);
                vB = fmaxf(vB, 0.f);
                sumB = fmaf(wo, vB, sumB);
            }
        }
#pragma unroll
        for (int off = 1; off < 4; off <<= 1) {
            sumA += __shfl_xor_sync(0xffffffffu, sumA, off);
            sumB += __shfl_xor_sync(0xffffffffu, sumB, off);
        }
        if (tg == 0) {
            int rowA = wm * 32 + tm * 16 + g;
            red[wn * 128 + rowA]     = sumA;
            red[wn * 128 + rowA + 8] = sumB;
        }
    }
    __syncthreads();

    if (tid < BM) {
        float tot = red[tid] + red[128 + tid];
        g_spart[nt * MDIM + mt * BM + tid] = tot;
    }
}

// ---------------------------------------------------------------------------
// Kernel 4: finalize — sum 8 partials + b_out, sigmoid -> score; argmax -> pos
// pos written as float values (0..16 exactly representable in fp32)
// ---------------------------------------------------------------------------
__global__ void finalize_kernel(const float* __restrict__ b_out, float* __restrict__ out) {
    __shared__ float sv[512];
    __shared__ int   si[512];
    int b = blockIdx.x;
    int tid = threadIdx.x;

    float s = -CUDART_INF_F;
    if (tid < NPIX) {
        float acc = b_out[0];
#pragma unroll
        for (int t = 0; t < NTILES; t++) acc += g_spart[t * MDIM + b * NPIX + tid];
        s = acc;
        out[b * NPIX + tid] = 1.f / (1.f + expf(-acc));   // sigmoid score
    }
    sv[tid] = s;
    si[tid] = tid;
    __syncthreads();
    for (int off = 256; off > 0; off >>= 1) {
        if (tid < off) {
            float v2 = sv[tid + off]; int i2 = si[tid + off];
            if (v2 > sv[tid] || (v2 == sv[tid] && i2 < si[tid])) {
                sv[tid] = v2; si[tid] = i2;
            }
        }
        __syncthreads();
    }
    if (tid == 0) {
        int idx = si[0];
        out[MDIM + b * 2 + 0] = (float)(idx / HW);   // y
        out[MDIM + b * 2 + 1] = (float)(idx % HW);   // x
    }
}

// ---------------------------------------------------------------------------
extern "C" void kernel_launch(void* const* d_in, const int* in_sizes, int n_in,
                              void* d_out, int out_size) {
    const float* x     = (const float*)d_in[0];
    const float* w_rnn = (const float*)d_in[1];
    const float* b_rnn = (const float*)d_in[2];
    const float* w_out = (const float*)d_in[3];
    const float* b_out = (const float*)d_in[4];
    float* out = (float*)d_out;

    cudaFuncSetAttribute(gemm_mma_kernel,
                         cudaFuncAttributeMaxDynamicSharedMemorySize, SMEM_TOT);

    transpose_x_split<<<dim3(8, 10, 128), dim3(32, 8)>>>(x);
    w_split_kernel<<<(NDIM * KDIM + 255) / 256, 256>>>(w_rnn);
    gemm_mma_kernel<<<dim3(NTILES, MTILES), 256, SMEM_TOT>>>(b_rnn, w_out);
    finalize_kernel<<<BATCH, 512>>>(b_out, out);
}